// round 7
// baseline (speedup 1.0000x reference)
#include <cuda_runtime.h>
#include <cuda_bf16.h>
#include <stdint.h>

#define SQ   2048
#define DM   1024
#define NH   16
#define HDD  64
#define NK   64

// fp32 hidden buffer (attn gathers from this)
__device__ float g_h[SQ * DM];
// bf16 hi/lo operand copies
__device__ __nv_bfloat16 g_xh[SQ * DM], g_xl[SQ * DM];
__device__ __nv_bfloat16 g_wih[DM * DM], g_wil[DM * DM];
__device__ __nv_bfloat16 g_woh[DM * DM], g_wol[DM * DM];
__device__ __nv_bfloat16 g_fh[SQ * DM], g_fl[SQ * DM];

// ---------------------------------------------------------------------------
// Split fp32 -> bf16 hi + bf16 lo
// ---------------------------------------------------------------------------
__global__ __launch_bounds__(256)
void cvt_split(const float* __restrict__ src,
               __nv_bfloat16* __restrict__ hi,
               __nv_bfloat16* __restrict__ lo, int n)
{
    const int i = (blockIdx.x * 256 + threadIdx.x) * 4;
    if (i >= n) return;
    float4 v = *(const float4*)(src + i);
    __nv_bfloat16 h0 = __float2bfloat16(v.x);
    __nv_bfloat16 h1 = __float2bfloat16(v.y);
    __nv_bfloat16 h2 = __float2bfloat16(v.z);
    __nv_bfloat16 h3 = __float2bfloat16(v.w);
    __nv_bfloat162 hv0; hv0.x = h0; hv0.y = h1;
    __nv_bfloat162 hv1; hv1.x = h2; hv1.y = h3;
    __nv_bfloat162 lv0, lv1;
    lv0.x = __float2bfloat16(v.x - __bfloat162float(h0));
    lv0.y = __float2bfloat16(v.y - __bfloat162float(h1));
    lv1.x = __float2bfloat16(v.z - __bfloat162float(h2));
    lv1.y = __float2bfloat16(v.w - __bfloat162float(h3));
    *(__nv_bfloat162*)(hi + i)     = hv0;
    *(__nv_bfloat162*)(hi + i + 2) = hv1;
    *(__nv_bfloat162*)(lo + i)     = lv0;
    *(__nv_bfloat162*)(lo + i + 2) = lv1;
}

// ---------------------------------------------------------------------------
// bf16x3 NT GEMM, cp.async double-buffered. Tile 128(M)x64(N)xBK32,
// 256 threads, 8 warps (4x2), warp tile 32x32 (mt=2, nt=4).
// grid (16,16) = 256 CTAs -> ~2 CTAs/SM resident, 4 warps/SMSP.
// smem row stride 40 bf16 -> conflict-free fragment LDS.
// ---------------------------------------------------------------------------
#define SROW  40
#define AELEM (128 * SROW)
#define BELEM (64 * SROW)
#define BUFELEM (2 * AELEM + 2 * BELEM)     // 15360 elems
#define GSMEM (2 * BUFELEM * 2)             // 61440 bytes

__device__ __forceinline__ void cp16(uint32_t sdst, const void* gsrc) {
    asm volatile("cp.async.cg.shared.global [%0], [%1], 16;" ::
                 "r"(sdst), "l"(gsrc));
}
__device__ __forceinline__ void cp_commit() {
    asm volatile("cp.async.commit_group;");
}
__device__ __forceinline__ void mma_bf16(float* c, const uint32_t* a, const uint32_t* b) {
    asm volatile(
        "mma.sync.aligned.m16n8k16.row.col.f32.bf16.bf16.f32 "
        "{%0,%1,%2,%3}, {%4,%5,%6,%7}, {%8,%9}, {%0,%1,%2,%3};"
        : "+f"(c[0]), "+f"(c[1]), "+f"(c[2]), "+f"(c[3])
        : "r"(a[0]), "r"(a[1]), "r"(a[2]), "r"(a[3]), "r"(b[0]), "r"(b[1]));
}

template <bool EPI>
__global__ __launch_bounds__(256, 2)
void gemm_bf16x3(const __nv_bfloat16* __restrict__ Ah,
                 const __nv_bfloat16* __restrict__ Al,
                 const __nv_bfloat16* __restrict__ Bh,
                 const __nv_bfloat16* __restrict__ Bl,
                 float* __restrict__ C,
                 const float* __restrict__ bias,
                 const float* __restrict__ resid)
{
    constexpr int KD = 1024, NC = 1024, NS = 32;

    extern __shared__ __nv_bfloat16 sm[];
    uint32_t sbase;
    asm("{ .reg .u64 t; cvta.to.shared.u64 t, %1; cvt.u32.u64 %0, t; }"
        : "=r"(sbase) : "l"(sm));

    const int t    = threadIdx.x;
    const int lane = t & 31;
    const int w    = t >> 5;
    const int wm   = w >> 1;          // 0..3 -> rows wm*32
    const int wn   = w & 1;           // 0..1 -> cols wn*32
    const int bm   = blockIdx.y;
    const int bn   = blockIdx.x;
    const int r4   = lane >> 2;
    const int c4   = lane & 3;

    const __nv_bfloat16* gsrc[4] = {
        Ah + (size_t)(bm * 128) * KD, Al + (size_t)(bm * 128) * KD,
        Bh + (size_t)(bn * 64) * KD,  Bl + (size_t)(bn * 64) * KD };

    float acc[2][4][4];
#pragma unroll
    for (int i = 0; i < 2; i++)
#pragma unroll
        for (int j = 0; j < 4; j++)
#pragma unroll
            for (int q = 0; q < 4; q++) acc[i][j][q] = 0.f;

    auto issue_stage = [&](int ks, int buf) {
        const int k0 = ks * 32;
        const uint32_t sb0 = sbase + (uint32_t)(buf * BUFELEM) * 2;
        // A arrays: 512 chunks each (128 rows x 4 x 16B)
#pragma unroll
        for (int arr = 0; arr < 2; arr++) {
            const uint32_t ab = sb0 + (uint32_t)(arr * AELEM) * 2;
            const __nv_bfloat16* src = gsrc[arr];
#pragma unroll
            for (int i = 0; i < 2; i++) {
                const int c = t + i * 256;
                const int row = c >> 2, j = c & 3;
                cp16(ab + (uint32_t)(row * SROW + j * 8) * 2,
                     src + (size_t)row * KD + k0 + j * 8);
            }
        }
        // B arrays: 256 chunks each (64 rows x 4 x 16B)
#pragma unroll
        for (int arr = 0; arr < 2; arr++) {
            const uint32_t ab = sb0 + (uint32_t)(2 * AELEM + arr * BELEM) * 2;
            const __nv_bfloat16* src = gsrc[2 + arr];
            const int row = t >> 2, j = t & 3;
            cp16(ab + (uint32_t)(row * SROW + j * 8) * 2,
                 src + (size_t)row * KD + k0 + j * 8);
        }
        cp_commit();
    };

    issue_stage(0, 0);

    for (int ks = 0; ks < NS; ks++) {
        const int buf = ks & 1;
        if (ks + 1 < NS) {
            issue_stage(ks + 1, buf ^ 1);
            asm volatile("cp.async.wait_group 1;");
        } else {
            asm volatile("cp.async.wait_group 0;");
        }
        __syncthreads();

        const __nv_bfloat16* sAh = sm + buf * BUFELEM;
        const __nv_bfloat16* sAl = sAh + AELEM;
        const __nv_bfloat16* sBh = sAl + AELEM;
        const __nv_bfloat16* sBl = sBh + BELEM;

#pragma unroll
        for (int kk = 0; kk < 2; kk++) {
            const int kc = kk * 16 + 2 * c4;
            uint32_t bh[4][2], bl[4][2];
#pragma unroll
            for (int nt = 0; nt < 4; nt++) {
                const int n0 = wn * 32 + nt * 8 + r4;
                bh[nt][0] = *(const uint32_t*)(sBh + n0 * SROW + kc);
                bh[nt][1] = *(const uint32_t*)(sBh + n0 * SROW + kc + 8);
                bl[nt][0] = *(const uint32_t*)(sBl + n0 * SROW + kc);
                bl[nt][1] = *(const uint32_t*)(sBl + n0 * SROW + kc + 8);
            }
#pragma unroll
            for (int mt = 0; mt < 2; mt++) {
                const int m0 = wm * 32 + mt * 16 + r4;
                uint32_t ah[4], al[4];
                ah[0] = *(const uint32_t*)(sAh + m0 * SROW + kc);
                ah[1] = *(const uint32_t*)(sAh + (m0 + 8) * SROW + kc);
                ah[2] = *(const uint32_t*)(sAh + m0 * SROW + kc + 8);
                ah[3] = *(const uint32_t*)(sAh + (m0 + 8) * SROW + kc + 8);
                al[0] = *(const uint32_t*)(sAl + m0 * SROW + kc);
                al[1] = *(const uint32_t*)(sAl + (m0 + 8) * SROW + kc);
                al[2] = *(const uint32_t*)(sAl + m0 * SROW + kc + 8);
                al[3] = *(const uint32_t*)(sAl + (m0 + 8) * SROW + kc + 8);
#pragma unroll
                for (int nt = 0; nt < 4; nt++) {
                    mma_bf16(acc[mt][nt], ah, bh[nt]);
                    mma_bf16(acc[mt][nt], ah, bl[nt]);
                    mma_bf16(acc[mt][nt], al, bh[nt]);
                }
            }
        }
        __syncthreads();
    }

    // Epilogue
#pragma unroll
    for (int mt = 0; mt < 2; mt++) {
#pragma unroll
        for (int nt = 0; nt < 4; nt++) {
            const int row0 = bm * 128 + wm * 32 + mt * 16 + r4;
            const int col  = bn * 64 + wn * 32 + nt * 8 + c4 * 2;
            float2 v0 = make_float2(acc[mt][nt][0], acc[mt][nt][1]);
            float2 v1 = make_float2(acc[mt][nt][2], acc[mt][nt][3]);
            if (EPI) {
                float2 bv = *(const float2*)(bias + col);
                float2 r0 = *(const float2*)(resid + (size_t)row0 * NC + col);
                float2 r1 = *(const float2*)(resid + (size_t)(row0 + 8) * NC + col);
                v0.x += bv.x + r0.x;  v0.y += bv.y + r0.y;
                v1.x += bv.x + r1.x;  v1.y += bv.y + r1.y;
            }
            *(float2*)(C + (size_t)row0 * NC + col)       = v0;
            *(float2*)(C + (size_t)(row0 + 8) * NC + col) = v1;
        }
    }
}

// ---------------------------------------------------------------------------
// Attention-fusion: 4 heads per block, 256 threads, one token per block.
// Gather rows are 1KB contiguous (4 head slices); per-head nb arrays keep
// the conflict-free [k][68] layout. Dynamic smem ~72KB -> 3 CTAs/SM.
// ---------------------------------------------------------------------------
#define NBS   68
#define NBGS  (NK * NBS)                       // 4352 floats per head array
#define ASMEM (256 + 1024 + 1024 + 4 * NBGS * 4)   // 71936 bytes

__global__ __launch_bounds__(256)
void attn_kernel(const float* __restrict__ hbuf,
                 const int32_t* __restrict__ routes,
                 __nv_bfloat16* __restrict__ fh,
                 __nv_bfloat16* __restrict__ fl)
{
    extern __shared__ char smraw[];
    int*   rt = (int*)smraw;                 // 64
    float* q  = (float*)(smraw + 256);       // 256
    float* sc = q + 256;                     // 256
    float* nb = sc + 256;                    // 4 * 64 * 68

    const int s  = blockIdx.x;
    const int hp = blockIdx.y;               // head group: heads 4hp..4hp+3
    const int t  = threadIdx.x;

    if (t < NK) rt[t] = routes[(size_t)s * NK + t] & (SQ - 1);
    q[t] = hbuf[(size_t)s * DM + hp * 256 + t];
    __syncthreads();

    // Gather: pass p loads rows p*4+rg; 64 lanes cover the 1KB row slice.
    const int rg = t >> 6;        // 0..3 row-in-pass
    const int l  = t & 63;        // lane within row
    const int gg = l >> 4;        // head sub-index of this lane's float4
    const int cc = (l & 15) * 4;  // within-head col
#pragma unroll
    for (int p = 0; p < 16; p++) {
        const int k = p * 4 + rg;
        const float* np = hbuf + (size_t)rt[k] * DM + hp * 256;
        float4 v = *(const float4*)(np + l * 4);
        *(float4*)&nb[gg * NBGS + k * NBS + cc] = v;
    }
    __syncthreads();

    // Scores: thread t -> head g2 = t>>6, neighbor k2 = t&63
    const int g2 = t >> 6;
    const int k2 = t & 63;
    const float* nrow = &nb[g2 * NBGS + k2 * NBS];
    const float* qg   = &q[g2 * 64];
    float dot = 0.f;
#pragma unroll
    for (int d0 = 0; d0 < HDD; d0 += 4) {
        float4 v  = *(const float4*)(nrow + d0);
        float4 qv = *(const float4*)(qg + d0);
        dot = fmaf(v.x, qv.x, dot);
        dot = fmaf(v.y, qv.y, dot);
        dot = fmaf(v.z, qv.z, dot);
        dot = fmaf(v.w, qv.w, dot);
    }
    sc[t] = dot * 0.125f;
    __syncthreads();

    float mx = -1e30f;
#pragma unroll
    for (int k = 0; k < NK; k++) mx = fmaxf(mx, sc[g2 * 64 + k]);
    const float wexp = expf(sc[t] - mx);
    __syncthreads();
    sc[t] = wexp;
    __syncthreads();

    // Weighted sum: thread t -> head g2, head-dim k2
    float sum = 0.f, accv = 0.f;
    const float* ng = &nb[g2 * NBGS];
#pragma unroll
    for (int k = 0; k < NK; k++) {
        const float wk = sc[g2 * 64 + k];
        sum  += wk;
        accv  = fmaf(wk, ng[k * NBS + k2], accv);
    }
    const float val = accv / sum;
    const size_t idx = (size_t)s * DM + hp * 256 + t;
    __nv_bfloat16 hv = __float2bfloat16(val);
    fh[idx] = hv;
    fl[idx] = __float2bfloat16(val - __bfloat162float(hv));
}

// ---------------------------------------------------------------------------
// Launch
// ---------------------------------------------------------------------------
extern "C" void kernel_launch(void* const* d_in, const int* in_sizes, int n_in,
                              void* d_out, int out_size)
{
    const float*   x      = nullptr;
    const int32_t* routes = nullptr;
    const float*   W_in   = nullptr;
    const float*   W_out  = nullptr;
    const float*   b_out  = nullptr;

    for (int i = 0; i < n_in; i++) {
        const int sz = in_sizes[i];
        if      (sz == SQ * DM)  { x = (const float*)d_in[i]; }
        else if (sz == SQ * NK)  { routes = (const int32_t*)d_in[i]; }
        else if (sz == DM * DM)  { if (!W_in) W_in = (const float*)d_in[i];
                                   else       W_out = (const float*)d_in[i]; }
        else if (sz == DM)       { b_out = (const float*)d_in[i]; }
    }
    float* out = (float*)d_out;

    float *hbuf;
    __nv_bfloat16 *xh, *xl, *wih, *wil, *woh, *wol, *fh, *fl;
    cudaGetSymbolAddress((void**)&hbuf, g_h);
    cudaGetSymbolAddress((void**)&xh,  g_xh);  cudaGetSymbolAddress((void**)&xl,  g_xl);
    cudaGetSymbolAddress((void**)&wih, g_wih); cudaGetSymbolAddress((void**)&wil, g_wil);
    cudaGetSymbolAddress((void**)&woh, g_woh); cudaGetSymbolAddress((void**)&wol, g_wol);
    cudaGetSymbolAddress((void**)&fh,  g_fh);  cudaGetSymbolAddress((void**)&fl,  g_fl);

    cudaFuncSetAttribute(gemm_bf16x3<false>,
                         cudaFuncAttributeMaxDynamicSharedMemorySize, GSMEM);
    cudaFuncSetAttribute(gemm_bf16x3<true>,
                         cudaFuncAttributeMaxDynamicSharedMemorySize, GSMEM);
    cudaFuncSetAttribute(attn_kernel,
                         cudaFuncAttributeMaxDynamicSharedMemorySize, ASMEM);

    cvt_split<<<SQ * DM / 1024, 256>>>(x, xh, xl, SQ * DM);
    cvt_split<<<DM * DM / 1024, 256>>>(W_in, wih, wil, DM * DM);
    cvt_split<<<DM * DM / 1024, 256>>>(W_out, woh, wol, DM * DM);

    dim3 gGemm(DM / 64, SQ / 128);   // (16, 16) = 256 CTAs

    gemm_bf16x3<false><<<gGemm, 256, GSMEM>>>(xh, xl, wih, wil, hbuf,
                                              nullptr, nullptr);
    attn_kernel<<<dim3(SQ, NH / 4), 256, ASMEM>>>(hbuf, routes, fh, fl);
    gemm_bf16x3<true><<<gGemm, 256, GSMEM>>>(fh, fl, woh, wol, out, b_out, x);
}

// round 8
// speedup vs baseline: 1.0906x; 1.0906x over previous
#include <cuda_runtime.h>
#include <cuda_bf16.h>
#include <stdint.h>

#define SQ   2048
#define DM   1024
#define NH   16
#define HDD  64
#define NK   64

// fp32 hidden buffer (attn gathers from this)
__device__ float g_h[SQ * DM];
// bf16 hi/lo operand copies
__device__ __nv_bfloat16 g_xh[SQ * DM], g_xl[SQ * DM];
__device__ __nv_bfloat16 g_wih[DM * DM], g_wil[DM * DM];
__device__ __nv_bfloat16 g_woh[DM * DM], g_wol[DM * DM];
__device__ __nv_bfloat16 g_fh[SQ * DM], g_fl[SQ * DM];

// ---------------------------------------------------------------------------
// Split fp32 -> bf16 hi + bf16 lo
// ---------------------------------------------------------------------------
__global__ __launch_bounds__(256)
void cvt_split(const float* __restrict__ src,
               __nv_bfloat16* __restrict__ hi,
               __nv_bfloat16* __restrict__ lo, int n)
{
    const int i = (blockIdx.x * 256 + threadIdx.x) * 4;
    if (i >= n) return;
    float4 v = *(const float4*)(src + i);
    __nv_bfloat16 h0 = __float2bfloat16(v.x);
    __nv_bfloat16 h1 = __float2bfloat16(v.y);
    __nv_bfloat16 h2 = __float2bfloat16(v.z);
    __nv_bfloat16 h3 = __float2bfloat16(v.w);
    __nv_bfloat162 hv0; hv0.x = h0; hv0.y = h1;
    __nv_bfloat162 hv1; hv1.x = h2; hv1.y = h3;
    __nv_bfloat162 lv0, lv1;
    lv0.x = __float2bfloat16(v.x - __bfloat162float(h0));
    lv0.y = __float2bfloat16(v.y - __bfloat162float(h1));
    lv1.x = __float2bfloat16(v.z - __bfloat162float(h2));
    lv1.y = __float2bfloat16(v.w - __bfloat162float(h3));
    *(__nv_bfloat162*)(hi + i)     = hv0;
    *(__nv_bfloat162*)(hi + i + 2) = hv1;
    *(__nv_bfloat162*)(lo + i)     = lv0;
    *(__nv_bfloat162*)(lo + i + 2) = lv1;
}

// ---------------------------------------------------------------------------
// bf16x3 NT GEMM, cp.async double-buffered. Tile 128x128xBK32,
// 512 threads / 16 warps (4x4), warp tile 32x32 -> 4 warps per SMSP
// to cover LDS+HMMA latency (R5 had only 2 and stalled at tensor=43%).
// smem row stride 40 bf16 -> conflict-free fragment LDS.
// ---------------------------------------------------------------------------
#define SROW 40
#define AELEM (128 * SROW)
#define BUFELEM (4 * AELEM)
#define GSMEM (2 * BUFELEM * 2)

__device__ __forceinline__ void cp16(uint32_t sdst, const void* gsrc) {
    asm volatile("cp.async.cg.shared.global [%0], [%1], 16;" ::
                 "r"(sdst), "l"(gsrc));
}
__device__ __forceinline__ void cp_commit() {
    asm volatile("cp.async.commit_group;");
}
__device__ __forceinline__ void mma_bf16(float* c, const uint32_t* a, const uint32_t* b) {
    asm volatile(
        "mma.sync.aligned.m16n8k16.row.col.f32.bf16.bf16.f32 "
        "{%0,%1,%2,%3}, {%4,%5,%6,%7}, {%8,%9}, {%0,%1,%2,%3};"
        : "+f"(c[0]), "+f"(c[1]), "+f"(c[2]), "+f"(c[3])
        : "r"(a[0]), "r"(a[1]), "r"(a[2]), "r"(a[3]), "r"(b[0]), "r"(b[1]));
}

template <bool EPI>
__global__ __launch_bounds__(512, 1)
void gemm_bf16x3(const __nv_bfloat16* __restrict__ Ah,
                 const __nv_bfloat16* __restrict__ Al,
                 const __nv_bfloat16* __restrict__ Bh,
                 const __nv_bfloat16* __restrict__ Bl,
                 float* __restrict__ C,
                 const float* __restrict__ bias,
                 const float* __restrict__ resid)
{
    constexpr int KD = 1024, NC = 1024, NS = 32;

    extern __shared__ __nv_bfloat16 sm[];
    uint32_t sbase;
    asm("{ .reg .u64 t; cvta.to.shared.u64 t, %1; cvt.u32.u64 %0, t; }"
        : "=r"(sbase) : "l"(sm));

    const int t    = threadIdx.x;
    const int lane = t & 31;
    const int w    = t >> 5;          // 0..15
    const int wm   = w >> 2;          // 0..3 -> rows wm*32
    const int wn   = w & 3;           // 0..3 -> cols wn*32
    const int bm   = blockIdx.y;
    const int bn   = blockIdx.x;
    const int r4   = lane >> 2;
    const int c4   = lane & 3;

    const __nv_bfloat16* gsrc[4] = {
        Ah + (size_t)(bm * 128) * KD, Al + (size_t)(bm * 128) * KD,
        Bh + (size_t)(bn * 128) * KD, Bl + (size_t)(bn * 128) * KD };

    float acc[2][4][4];
#pragma unroll
    for (int i = 0; i < 2; i++)
#pragma unroll
        for (int j = 0; j < 4; j++)
#pragma unroll
            for (int q = 0; q < 4; q++) acc[i][j][q] = 0.f;

    // Per stage: 4 arrays x 512 16B-chunks; each thread does 1 chunk/array.
    const int crow = t >> 2;          // 0..127
    const int cj   = t & 3;           // 16B unit within 64B row
    auto issue_stage = [&](int ks, int buf) {
        const int k0 = ks * 32;
#pragma unroll
        for (int arr = 0; arr < 4; arr++) {
            const uint32_t ab = sbase + (uint32_t)(buf * BUFELEM + arr * AELEM) * 2;
            cp16(ab + (uint32_t)(crow * SROW + cj * 8) * 2,
                 gsrc[arr] + (size_t)crow * KD + k0 + cj * 8);
        }
        cp_commit();
    };

    issue_stage(0, 0);

    for (int ks = 0; ks < NS; ks++) {
        const int buf = ks & 1;
        if (ks + 1 < NS) {
            issue_stage(ks + 1, buf ^ 1);
            asm volatile("cp.async.wait_group 1;");
        } else {
            asm volatile("cp.async.wait_group 0;");
        }
        __syncthreads();

        const __nv_bfloat16* sAh = sm + buf * BUFELEM;
        const __nv_bfloat16* sAl = sAh + AELEM;
        const __nv_bfloat16* sBh = sAl + AELEM;
        const __nv_bfloat16* sBl = sBh + AELEM;

#pragma unroll
        for (int kk = 0; kk < 2; kk++) {
            const int kc = kk * 16 + 2 * c4;
            uint32_t bh[4][2], bl[4][2];
#pragma unroll
            for (int nt = 0; nt < 4; nt++) {
                const int n0 = wn * 32 + nt * 8 + r4;
                bh[nt][0] = *(const uint32_t*)(sBh + n0 * SROW + kc);
                bh[nt][1] = *(const uint32_t*)(sBh + n0 * SROW + kc + 8);
                bl[nt][0] = *(const uint32_t*)(sBl + n0 * SROW + kc);
                bl[nt][1] = *(const uint32_t*)(sBl + n0 * SROW + kc + 8);
            }
#pragma unroll
            for (int mt = 0; mt < 2; mt++) {
                const int m0 = wm * 32 + mt * 16 + r4;
                uint32_t ah[4], al[4];
                ah[0] = *(const uint32_t*)(sAh + m0 * SROW + kc);
                ah[1] = *(const uint32_t*)(sAh + (m0 + 8) * SROW + kc);
                ah[2] = *(const uint32_t*)(sAh + m0 * SROW + kc + 8);
                ah[3] = *(const uint32_t*)(sAh + (m0 + 8) * SROW + kc + 8);
                al[0] = *(const uint32_t*)(sAl + m0 * SROW + kc);
                al[1] = *(const uint32_t*)(sAl + (m0 + 8) * SROW + kc);
                al[2] = *(const uint32_t*)(sAl + m0 * SROW + kc + 8);
                al[3] = *(const uint32_t*)(sAl + (m0 + 8) * SROW + kc + 8);
#pragma unroll
                for (int nt = 0; nt < 4; nt++) {
                    mma_bf16(acc[mt][nt], ah, bh[nt]);
                    mma_bf16(acc[mt][nt], ah, bl[nt]);
                    mma_bf16(acc[mt][nt], al, bh[nt]);
                }
            }
        }
        __syncthreads();
    }

    // Epilogue
#pragma unroll
    for (int mt = 0; mt < 2; mt++) {
#pragma unroll
        for (int nt = 0; nt < 4; nt++) {
            const int row0 = bm * 128 + wm * 32 + mt * 16 + r4;
            const int col  = bn * 128 + wn * 32 + nt * 8 + c4 * 2;
            float2 v0 = make_float2(acc[mt][nt][0], acc[mt][nt][1]);
            float2 v1 = make_float2(acc[mt][nt][2], acc[mt][nt][3]);
            if (EPI) {
                float2 bv = *(const float2*)(bias + col);
                float2 r0 = *(const float2*)(resid + (size_t)row0 * NC + col);
                float2 r1 = *(const float2*)(resid + (size_t)(row0 + 8) * NC + col);
                v0.x += bv.x + r0.x;  v0.y += bv.y + r0.y;
                v1.x += bv.x + r1.x;  v1.y += bv.y + r1.y;
            }
            *(float2*)(C + (size_t)row0 * NC + col)       = v0;
            *(float2*)(C + (size_t)(row0 + 8) * NC + col) = v1;
        }
    }
}

// ---------------------------------------------------------------------------
// Attention-fusion, coalesced gather (reverted to R5's 64-thread version).
// ---------------------------------------------------------------------------
#define NBS 68
__global__ __launch_bounds__(64)
void attn_kernel(const float* __restrict__ hbuf,
                 const int32_t* __restrict__ routes,
                 __nv_bfloat16* __restrict__ fh,
                 __nv_bfloat16* __restrict__ fl)
{
    const int s  = blockIdx.x;
    const int hh = blockIdx.y;
    const int t  = threadIdx.x;

    __shared__ float nb[NK][NBS];
    __shared__ float q[HDD];
    __shared__ float sc[NK];
    __shared__ int   rt[NK];

    rt[t] = routes[(size_t)s * NK + t] & (SQ - 1);
    q[t]  = hbuf[(size_t)s * DM + hh * HDD + t];
    __syncthreads();

    const int g = t >> 4;
    const int i4 = (t & 15) * 4;
#pragma unroll
    for (int p = 0; p < 16; p++) {
        const int k = p * 4 + g;
        const float* np = hbuf + (size_t)rt[k] * DM + hh * HDD;
        *(float4*)&nb[k][i4] = *(const float4*)(np + i4);
    }
    __syncthreads();

    float dot = 0.f;
#pragma unroll
    for (int d0 = 0; d0 < HDD; d0 += 4) {
        float4 v  = *(const float4*)&nb[t][d0];
        float4 qv = *(const float4*)&q[d0];
        dot = fmaf(v.x, qv.x, dot);
        dot = fmaf(v.y, qv.y, dot);
        dot = fmaf(v.z, qv.z, dot);
        dot = fmaf(v.w, qv.w, dot);
    }
    sc[t] = dot * 0.125f;
    __syncthreads();

    float mx = -1e30f;
#pragma unroll
    for (int k = 0; k < NK; k++) mx = fmaxf(mx, sc[k]);
    const float wexp = expf(sc[t] - mx);
    __syncthreads();
    sc[t] = wexp;
    __syncthreads();

    float sum = 0.f, accv = 0.f;
#pragma unroll
    for (int k = 0; k < NK; k++) {
        const float wk = sc[k];
        sum  += wk;
        accv  = fmaf(wk, nb[k][t], accv);
    }
    const float val = accv / sum;
    const size_t idx = (size_t)s * DM + hh * HDD + t;
    __nv_bfloat16 hv = __float2bfloat16(val);
    fh[idx] = hv;
    fl[idx] = __float2bfloat16(val - __bfloat162float(hv));
}

// ---------------------------------------------------------------------------
// Launch
// ---------------------------------------------------------------------------
extern "C" void kernel_launch(void* const* d_in, const int* in_sizes, int n_in,
                              void* d_out, int out_size)
{
    const float*   x      = nullptr;
    const int32_t* routes = nullptr;
    const float*   W_in   = nullptr;
    const float*   W_out  = nullptr;
    const float*   b_out  = nullptr;

    for (int i = 0; i < n_in; i++) {
        const int sz = in_sizes[i];
        if      (sz == SQ * DM)  { x = (const float*)d_in[i]; }
        else if (sz == SQ * NK)  { routes = (const int32_t*)d_in[i]; }
        else if (sz == DM * DM)  { if (!W_in) W_in = (const float*)d_in[i];
                                   else       W_out = (const float*)d_in[i]; }
        else if (sz == DM)       { b_out = (const float*)d_in[i]; }
    }
    float* out = (float*)d_out;

    float *hbuf;
    __nv_bfloat16 *xh, *xl, *wih, *wil, *woh, *wol, *fh, *fl;
    cudaGetSymbolAddress((void**)&hbuf, g_h);
    cudaGetSymbolAddress((void**)&xh,  g_xh);  cudaGetSymbolAddress((void**)&xl,  g_xl);
    cudaGetSymbolAddress((void**)&wih, g_wih); cudaGetSymbolAddress((void**)&wil, g_wil);
    cudaGetSymbolAddress((void**)&woh, g_woh); cudaGetSymbolAddress((void**)&wol, g_wol);
    cudaGetSymbolAddress((void**)&fh,  g_fh);  cudaGetSymbolAddress((void**)&fl,  g_fl);

    cudaFuncSetAttribute(gemm_bf16x3<false>,
                         cudaFuncAttributeMaxDynamicSharedMemorySize, GSMEM);
    cudaFuncSetAttribute(gemm_bf16x3<true>,
                         cudaFuncAttributeMaxDynamicSharedMemorySize, GSMEM);

    cvt_split<<<SQ * DM / 1024, 256>>>(x, xh, xl, SQ * DM);
    cvt_split<<<DM * DM / 1024, 256>>>(W_in, wih, wil, DM * DM);
    cvt_split<<<DM * DM / 1024, 256>>>(W_out, woh, wol, DM * DM);

    dim3 gGemm(DM / 128, SQ / 128);   // (8, 16) = 128 CTAs

    gemm_bf16x3<false><<<gGemm, 512, GSMEM>>>(xh, xl, wih, wil, hbuf,
                                              nullptr, nullptr);
    attn_kernel<<<dim3(SQ, NH), 64>>>(hbuf, routes, fh, fl);
    gemm_bf16x3<true><<<gGemm, 512, GSMEM>>>(fh, fl, woh, wol, out, b_out, x);
}